// round 4
// baseline (speedup 1.0000x reference)
#include <cuda_runtime.h>
#include <cuda_fp16.h>
#include <math.h>

#define SVAL 64
#define DIM 256
#define VOXELS (DIM * DIM * DIM)

// Scratch: per voxel 4 halves = (v[y,x], v[y,x+1], v[y+1,x], v[y+1,x+1]),
// neighbors clamped at build time (masked at sample time). 8B/voxel = 134MB.
__device__ uint2 g_dup4[VOXELS];

__global__ __launch_bounds__(256) void build_dup4_kernel(const float* __restrict__ vol)
{
    const int bid = blockIdx.x;              // 16384 blocks
    const int tid = threadIdx.x;
    const int z  = bid >> 6;                 // [0,256)
    const int y  = ((bid & 63) << 2) + (tid >> 6);   // 4 rows per block
    const int xq = (tid & 63) << 2;          // 4 x per thread

    const float* row0 = vol + ((size_t)z * DIM + y) * DIM;
    const float* row1 = vol + ((size_t)z * DIM + min(y + 1, DIM - 1)) * DIM;

    const float4 a = __ldg((const float4*)(row0 + xq));
    const float4 b = __ldg((const float4*)(row1 + xq));
    const float ae = __ldg(row0 + min(xq + 4, DIM - 1));
    const float be = __ldg(row1 + min(xq + 4, DIM - 1));

    __half2 a01 = __floats2half2_rn(a.x, a.y), b01 = __floats2half2_rn(b.x, b.y);
    __half2 a12 = __floats2half2_rn(a.y, a.z), b12 = __floats2half2_rn(b.y, b.z);
    __half2 a23 = __floats2half2_rn(a.z, a.w), b23 = __floats2half2_rn(b.z, b.w);
    __half2 a3e = __floats2half2_rn(a.w, ae ), b3e = __floats2half2_rn(b.w, be );

    uint4 o0, o1;
    o0.x = *(unsigned*)&a01; o0.y = *(unsigned*)&b01;
    o0.z = *(unsigned*)&a12; o0.w = *(unsigned*)&b12;
    o1.x = *(unsigned*)&a23; o1.y = *(unsigned*)&b23;
    o1.z = *(unsigned*)&a3e; o1.w = *(unsigned*)&b3e;

    uint4* out = (uint4*)(g_dup4 + ((size_t)z * DIM + y) * DIM + xq);
    out[0] = o0;
    out[1] = o1;
}

__global__ __launch_bounds__(256) void psf_sample_kernel(
    const float* __restrict__ sampleGrid, // [N,3]
    const float* __restrict__ ax,         // [N,6]
    const float* __restrict__ bound,      // [N,2,3]
    const float* __restrict__ invcov,     // [3,3]
    const float* __restrict__ xyz_psf,    // [N,S,3]
    float* __restrict__ out,              // [N]
    int N)
{
    __shared__ float s_psf[8][SVAL * 3];  // 192 floats per warp

    const int wib = threadIdx.x >> 5;     // warp in block
    const int n = blockIdx.x * (blockDim.x >> 5) + wib;
    if (n >= N) return;
    const int lane = threadIdx.x & 31;

    // ---- stage psf points through smem (coalesced LDG, conflict-free LDS) ----
    {
        const float* pb = xyz_psf + (size_t)n * SVAL * 3;
#pragma unroll
        for (int k = 0; k < 6; k++)
            s_psf[wib][lane + 32 * k] = __ldg(pb + lane + 32 * k);
    }
    __syncwarp();

    // ---- per-ray uniform setup ----
    const float vx = __ldg(ax + (size_t)n * 6 + 0);
    const float vy = __ldg(ax + (size_t)n * 6 + 1);
    const float vz = __ldg(ax + (size_t)n * 6 + 2);
    const float tx = __ldg(ax + (size_t)n * 6 + 3);
    const float ty = __ldg(ax + (size_t)n * 6 + 4);
    const float tz = __ldg(ax + (size_t)n * 6 + 5);

    const float theta = sqrtf(vx * vx + vy * vy + vz * vz);
    const float invt = 1.0f / fmaxf(theta, 1e-12f);
    const float kx = vx * invt, ky = vy * invt, kz = vz * invt;
    const float st = sinf(theta);
    const float ct = cosf(theta);
    const float oc = 1.0f - ct;

    const float r00 = 1.0f - oc * (ky * ky + kz * kz);
    const float r01 = -st * kz + oc * kx * ky;
    const float r02 =  st * ky + oc * kx * kz;
    const float r10 =  st * kz + oc * kx * ky;
    const float r11 = 1.0f - oc * (kx * kx + kz * kz);
    const float r12 = -st * kx + oc * ky * kz;
    const float r20 = -st * ky + oc * kx * kz;
    const float r21 =  st * kx + oc * ky * kz;
    const float r22 = 1.0f - oc * (kx * kx + ky * ky);

    const float sgx = __ldg(sampleGrid + (size_t)n * 3 + 0);
    const float sgy = __ldg(sampleGrid + (size_t)n * 3 + 1);
    const float sgz = __ldg(sampleGrid + (size_t)n * 3 + 2);

    const float px = sgx + tx, py = sgy + ty, pz = sgz + tz;
    const float cx = r00 * px + r01 * py + r02 * pz;
    const float cy = r10 * px + r11 * py + r12 * pz;
    const float cz = r20 * px + r21 * py + r22 * pz;

    const float hx = 0.5f * (__ldg(bound + (size_t)n * 6 + 3) - __ldg(bound + (size_t)n * 6 + 0));
    const float hy = 0.5f * (__ldg(bound + (size_t)n * 6 + 4) - __ldg(bound + (size_t)n * 6 + 1));
    const float hz = 0.5f * (__ldg(bound + (size_t)n * 6 + 5) - __ldg(bound + (size_t)n * 6 + 2));

    const float c00 = __ldg(invcov + 0), c01 = __ldg(invcov + 1), c02 = __ldg(invcov + 2);
    const float c10 = __ldg(invcov + 3), c11 = __ldg(invcov + 4), c12 = __ldg(invcov + 5);
    const float c20 = __ldg(invcov + 6), c21 = __ldg(invcov + 7), c22 = __ldg(invcov + 8);

    float sum_vw = 0.0f;
    float sum_w = 0.0f;

    const float SCL = 256.0f / 255.0f;   // pix = world*SCL - 0.5

#pragma unroll
    for (int rep = 0; rep < 2; rep++) {
        const int s = lane + rep * 32;
        const float ex = s_psf[wib][3 * s + 0] * hx;
        const float ey = s_psf[wib][3 * s + 1] * hy;
        const float ez = s_psf[wib][3 * s + 2] * hz;

        const float pixx = fmaf(cx + ex, SCL, -0.5f);
        const float pixy = fmaf(cy + ey, SCL, -0.5f);
        const float pixz = fmaf(cz + ez, SCL, -0.5f);

        const float fx0 = floorf(pixx), fy0 = floorf(pixy), fz0 = floorf(pixz);
        const int x0 = (int)fx0, y0 = (int)fy0, z0 = (int)fz0;
        const float fx = pixx - fx0, fy = pixy - fy0, fz = pixz - fz0;

        const bool xin = (x0 >= 0);
        const bool xv0 = xin & (x0 < DIM);
        const bool xv1 = (x0 >= -1) & (x0 < DIM - 1);
        const bool yin = (y0 >= 0);
        const bool yv0 = yin & (y0 < DIM);
        const bool yv1 = (y0 >= -1) & (y0 < DIM - 1);
        const bool zv0 = (z0 >= 0) & (z0 < DIM);
        const bool zv1 = (z0 >= -1) & (z0 < DIM - 1);

        const int xc  = min(max(x0, 0), DIM - 1);
        const int yc  = min(max(y0, 0), DIM - 1);
        const int zc0 = min(max(z0, 0), DIM - 1);
        const int zc1 = min(max(z0 + 1, 0), DIM - 1);

        const int base0 = (zc0 * DIM + yc) * DIM + xc;
        const int base1 = (zc1 * DIM + yc) * DIM + xc;

        const uint2 ZU = make_uint2(0u, 0u);
        const uint2 d0 = zv0 ? __ldg(g_dup4 + base0) : ZU;
        const uint2 d1 = zv1 ? __ldg(g_dup4 + base1) : ZU;

        // masked x-interp weights (handle x0 >= DIM via zero weight)
        const float wx0m = xv0 ? (1.0f - fx) : 0.0f;
        const float wx1m = xv1 ? fx : 0.0f;
        const float wy0m = yv0 ? (1.0f - fy) : 0.0f;
        const float wy1m = yv1 ? fy : 0.0f;

        float zl[2];
#pragma unroll
        for (int t = 0; t < 2; t++) {
            const unsigned plo = t ? d1.x : d0.x;   // (v[y,x], v[y,x+1])
            const unsigned phi = t ? d1.y : d0.y;   // (v[y+1,x], v[y+1,x+1])
            const float2 L = __half22float2(*(const __half2*)&plo);
            const float2 H = __half22float2(*(const __half2*)&phi);
            // y-row select: if y0 == -1, loaded row (at y=0) is the y1 row
            const float2 R0 = yin ? L : make_float2(0.f, 0.f);
            const float2 R1 = yin ? H : L;
            // x select within row: if x0 == -1, loaded .x (at x=0) is the x1 tap
            const float a0 = xin ? R0.x : 0.f;
            const float b0 = xin ? R0.y : R0.x;
            const float a1 = xin ? R1.x : 0.f;
            const float b1 = xin ? R1.y : R1.x;
            const float xi0 = wx0m * a0 + wx1m * b0;
            const float xi1 = wx0m * a1 + wx1m * b1;
            zl[t] = wy0m * xi0 + wy1m * xi1;
        }
        const float val = fmaf(1.0f - fz, zl[0], fz * zl[1]);

        const float q =
            ex * (c00 * ex + c01 * ey + c02 * ez) +
            ey * (c10 * ex + c11 * ey + c12 * ez) +
            ez * (c20 * ex + c21 * ey + c22 * ez);
        const float w = __expf(-0.5f * q);

        sum_vw = fmaf(w, val, sum_vw);
        sum_w += w;
    }

#pragma unroll
    for (int off = 16; off > 0; off >>= 1) {
        sum_vw += __shfl_xor_sync(0xFFFFFFFFu, sum_vw, off);
        sum_w  += __shfl_xor_sync(0xFFFFFFFFu, sum_w, off);
    }

    if (lane == 0) {
        out[n] = sum_vw / sum_w;
    }
}

extern "C" void kernel_launch(void* const* d_in, const int* in_sizes, int n_in,
                              void* d_out, int out_size)
{
    const float* x          = (const float*)d_in[0];
    const float* sampleGrid = (const float*)d_in[1];
    const float* ax         = (const float*)d_in[2];
    const float* bound      = (const float*)d_in[3];
    const float* invcov     = (const float*)d_in[4];
    const float* xyz_psf    = (const float*)d_in[5];
    float* out = (float*)d_out;

    const int N = in_sizes[1] / 3;

    // Pre-pass: build x/y-duplicated half volume (one block per 4 rows)
    build_dup4_kernel<<<DIM * (DIM / 4), 256>>>(x);

    // Main kernel: warp per ray
    {
        const int threads = 256;
        const int warps_per_block = threads / 32;
        const int blocks = (N + warps_per_block - 1) / warps_per_block;
        psf_sample_kernel<<<blocks, threads>>>(sampleGrid, ax, bound, invcov,
                                               xyz_psf, out, N);
    }
}

// round 5
// speedup vs baseline: 1.2853x; 1.2853x over previous
#include <cuda_runtime.h>
#include <cuda_fp16.h>
#include <math.h>

#define SVAL 64
#define DIM 256
#define VOXELS (DIM * DIM * DIM)

// Scratch: pair-duplicated half volume. dup[i] = (vol[i], vol[i+1 within row]).
// 4B/voxel = 67MB -> fits in L2 (126MB). This is load-bearing: random gathers
// must be served from L2, not DRAM.
__device__ __half2 g_dup[VOXELS];

__global__ __launch_bounds__(256) void build_dup_kernel(const float* __restrict__ vol)
{
    const int t = blockIdx.x * blockDim.x + threadIdx.x; // one thread per 4 voxels
    if (t >= VOXELS / 4) return;
    const int base = t * 4;
    const float4 v = __ldg((const float4*)(vol + base));
    const int x = base & (DIM - 1);
    const float nxt = (x == DIM - 4) ? v.w : __ldg(vol + base + 4);

    __half2 h0 = __floats2half2_rn(v.x, v.y);
    __half2 h1 = __floats2half2_rn(v.y, v.z);
    __half2 h2 = __floats2half2_rn(v.z, v.w);
    __half2 h3 = __floats2half2_rn(v.w, nxt);

    uint4 p;
    p.x = *(unsigned int*)&h0;
    p.y = *(unsigned int*)&h1;
    p.z = *(unsigned int*)&h2;
    p.w = *(unsigned int*)&h3;
    ((uint4*)g_dup)[t] = p;
}

__global__ __launch_bounds__(256) void psf_sample_kernel(
    const float* __restrict__ sampleGrid, // [N,3]
    const float* __restrict__ ax,         // [N,6]
    const float* __restrict__ bound,      // [N,2,3]
    const float* __restrict__ invcov,     // [3,3]
    const float* __restrict__ xyz_psf,    // [N,S,3]
    float* __restrict__ out,              // [N]
    int N)
{
    __shared__ float s_psf[8][SVAL * 3];   // 6KB: per-warp psf staging

    const int wib = threadIdx.x >> 5;
    const int n = blockIdx.x * (blockDim.x >> 5) + wib;
    if (n >= N) return;
    const int lane = threadIdx.x & 31;

    // ---- stage psf points: coalesced streaming loads -> smem ----
    {
        const float* pb = xyz_psf + (size_t)n * SVAL * 3;
#pragma unroll
        for (int k = 0; k < 6; k++)
            s_psf[wib][lane + 32 * k] = __ldcs(pb + lane + 32 * k);
    }
    __syncwarp();

    // ---- per-ray uniform setup (broadcast loads) ----
    const float vx = __ldg(ax + (size_t)n * 6 + 0);
    const float vy = __ldg(ax + (size_t)n * 6 + 1);
    const float vz = __ldg(ax + (size_t)n * 6 + 2);
    const float tx = __ldg(ax + (size_t)n * 6 + 3);
    const float ty = __ldg(ax + (size_t)n * 6 + 4);
    const float tz = __ldg(ax + (size_t)n * 6 + 5);

    const float theta = sqrtf(vx * vx + vy * vy + vz * vz);
    const float invt = 1.0f / fmaxf(theta, 1e-12f);
    const float kx = vx * invt, ky = vy * invt, kz = vz * invt;
    const float st = sinf(theta);
    const float ct = cosf(theta);
    const float oc = 1.0f - ct;

    const float r00 = 1.0f - oc * (ky * ky + kz * kz);
    const float r01 = -st * kz + oc * kx * ky;
    const float r02 =  st * ky + oc * kx * kz;
    const float r10 =  st * kz + oc * kx * ky;
    const float r11 = 1.0f - oc * (kx * kx + kz * kz);
    const float r12 = -st * kx + oc * ky * kz;
    const float r20 = -st * ky + oc * kx * kz;
    const float r21 =  st * kx + oc * ky * kz;
    const float r22 = 1.0f - oc * (kx * kx + ky * ky);

    const float sgx = __ldg(sampleGrid + (size_t)n * 3 + 0);
    const float sgy = __ldg(sampleGrid + (size_t)n * 3 + 1);
    const float sgz = __ldg(sampleGrid + (size_t)n * 3 + 2);

    const float px = sgx + tx, py = sgy + ty, pz = sgz + tz;
    const float cx = r00 * px + r01 * py + r02 * pz;
    const float cy = r10 * px + r11 * py + r12 * pz;
    const float cz = r20 * px + r21 * py + r22 * pz;

    const float hx = 0.5f * (__ldg(bound + (size_t)n * 6 + 3) - __ldg(bound + (size_t)n * 6 + 0));
    const float hy = 0.5f * (__ldg(bound + (size_t)n * 6 + 4) - __ldg(bound + (size_t)n * 6 + 1));
    const float hz = 0.5f * (__ldg(bound + (size_t)n * 6 + 5) - __ldg(bound + (size_t)n * 6 + 2));

    const float c00 = __ldg(invcov + 0), c01 = __ldg(invcov + 1), c02 = __ldg(invcov + 2);
    const float c10 = __ldg(invcov + 3), c11 = __ldg(invcov + 4), c12 = __ldg(invcov + 5);
    const float c20 = __ldg(invcov + 6), c21 = __ldg(invcov + 7), c22 = __ldg(invcov + 8);

    float sum_vw = 0.0f;
    float sum_w = 0.0f;

    const float SCL = 256.0f / 255.0f;   // pix = world*SCL - 0.5

#pragma unroll
    for (int rep = 0; rep < 2; rep++) {
        const int s = lane + rep * 32;
        const float ex = s_psf[wib][3 * s + 0] * hx;
        const float ey = s_psf[wib][3 * s + 1] * hy;
        const float ez = s_psf[wib][3 * s + 2] * hz;

        const float pixx = fmaf(cx + ex, SCL, -0.5f);
        const float pixy = fmaf(cy + ey, SCL, -0.5f);
        const float pixz = fmaf(cz + ez, SCL, -0.5f);

        const float fx0 = floorf(pixx), fy0 = floorf(pixy), fz0 = floorf(pixz);
        const int x0 = (int)fx0, y0 = (int)fy0, z0 = (int)fz0;
        const float fx = pixx - fx0, fy = pixy - fy0, fz = pixz - fz0;

        const bool xin = (x0 >= 0);
        const bool vx0 = xin & (x0 < DIM);
        const bool vx1 = (x0 >= -1) & (x0 < DIM - 1);
        const bool vy0 = (y0 >= 0) & (y0 < DIM);
        const bool vy1 = (y0 >= -1) & (y0 < DIM - 1);
        const bool vz0 = (z0 >= 0) & (z0 < DIM);
        const bool vz1 = (z0 >= -1) & (z0 < DIM - 1);

        const int xc0 = min(max(x0, 0), DIM - 1);
        const int yc0 = min(max(y0, 0), DIM - 1);
        const int yc1 = min(max(y0 + 1, 0), DIM - 1);
        const int zc0 = min(max(z0, 0), DIM - 1);
        const int zc1 = min(max(z0 + 1, 0), DIM - 1);

        const bool rv00 = vz0 & vy0;
        const bool rv01 = vz0 & vy1;
        const bool rv10 = vz1 & vy0;
        const bool rv11 = vz1 & vy1;

        const int b00 = (zc0 * DIM + yc0) * DIM + xc0;
        const int b01 = (zc0 * DIM + yc1) * DIM + xc0;
        const int b10 = (zc1 * DIM + yc0) * DIM + xc0;
        const int b11 = (zc1 * DIM + yc1) * DIM + xc0;

        const __half2 HZ = __float2half2_rn(0.0f);
        const __half2 d00 = rv00 ? __ldg(g_dup + b00) : HZ;
        const __half2 d01 = rv01 ? __ldg(g_dup + b01) : HZ;
        const __half2 d10 = rv10 ? __ldg(g_dup + b10) : HZ;
        const __half2 d11 = rv11 ? __ldg(g_dup + b11) : HZ;

        const float2 f00 = __half22float2(d00);
        const float2 f01 = __half22float2(d01);
        const float2 f10 = __half22float2(d10);
        const float2 f11 = __half22float2(d11);

        const float v000 = vx0 ? f00.x : 0.f;
        const float v001 = vx1 ? (xin ? f00.y : f00.x) : 0.f;
        const float v010 = vx0 ? f01.x : 0.f;
        const float v011 = vx1 ? (xin ? f01.y : f01.x) : 0.f;
        const float v100 = vx0 ? f10.x : 0.f;
        const float v101 = vx1 ? (xin ? f10.y : f10.x) : 0.f;
        const float v110 = vx0 ? f11.x : 0.f;
        const float v111 = vx1 ? (xin ? f11.y : f11.x) : 0.f;

        const float wx0 = 1.0f - fx, wy0 = 1.0f - fy, wz0 = 1.0f - fz;

        const float vz0p =
            wy0 * fmaf(wx0, v000, fx * v001) + fy * fmaf(wx0, v010, fx * v011);
        const float vz1p =
            wy0 * fmaf(wx0, v100, fx * v101) + fy * fmaf(wx0, v110, fx * v111);
        const float val = fmaf(wz0, vz0p, fz * vz1p);

        const float q =
            ex * (c00 * ex + c01 * ey + c02 * ez) +
            ey * (c10 * ex + c11 * ey + c12 * ez) +
            ez * (c20 * ex + c21 * ey + c22 * ez);
        const float w = __expf(-0.5f * q);

        sum_vw = fmaf(w, val, sum_vw);
        sum_w += w;
    }

#pragma unroll
    for (int off = 16; off > 0; off >>= 1) {
        sum_vw += __shfl_xor_sync(0xFFFFFFFFu, sum_vw, off);
        sum_w  += __shfl_xor_sync(0xFFFFFFFFu, sum_w, off);
    }

    if (lane == 0) {
        out[n] = sum_vw / sum_w;
    }
}

extern "C" void kernel_launch(void* const* d_in, const int* in_sizes, int n_in,
                              void* d_out, int out_size)
{
    const float* x          = (const float*)d_in[0];
    const float* sampleGrid = (const float*)d_in[1];
    const float* ax         = (const float*)d_in[2];
    const float* bound      = (const float*)d_in[3];
    const float* invcov     = (const float*)d_in[4];
    const float* xyz_psf    = (const float*)d_in[5];
    float* out = (float*)d_out;

    const int N = in_sizes[1] / 3;

    // Pre-pass: build pair-duplicated half2 volume (67MB, L2-resident)
    {
        const int threads = 256;
        const int work = VOXELS / 4;
        const int blocks = (work + threads - 1) / threads;
        build_dup_kernel<<<blocks, threads>>>(x);
    }

    // Main kernel: warp per ray
    {
        const int threads = 256;
        const int warps_per_block = threads / 32;
        const int blocks = (N + warps_per_block - 1) / warps_per_block;
        psf_sample_kernel<<<blocks, threads>>>(sampleGrid, ax, bound, invcov,
                                               xyz_psf, out, N);
    }
}